// round 5
// baseline (speedup 1.0000x reference)
#include <cuda_runtime.h>
#include <cstdint>

// ---------------------------------------------------------------------------
// MultiHeadAttention: B=4, T=2048, C=1024, H=16, hs=64 (fp32 I/O)
// Round 5: 3-stage cp.async GEMM pipeline; V stored transposed [b,h,d,t] so
// attention PV uses LDSM B-fragments symmetric with QK^T. All tf32 mma.sync.
// ---------------------------------------------------------------------------

#define BATCH   4
#define T_SEQ   2048
#define NH      16
#define HS      64
#define CDIM    1024
#define MROWS   (BATCH * T_SEQ)          // 8192

// Scratch (device globals). All hold tf32-bit-pattern floats.
__device__ float g_xa[MROWS * CDIM];                // x, tf32
__device__ float g_wqkv[3 * CDIM * CDIM];           // W_qkv, tf32
__device__ float g_wout[CDIM * CDIM];               // W_out, tf32
__device__ float g_q[BATCH * NH * T_SEQ * HS];      // [b,h,t,d], tf32, scaled
__device__ float g_k[BATCH * NH * T_SEQ * HS];      // [b,h,t,d], tf32
__device__ float g_v[BATCH * NH * HS * T_SEQ];      // [b,h,d,t]  (transposed!)
__device__ float g_attv[BATCH * T_SEQ * CDIM];      // [b,t,h*hs+d], tf32

// ---------------------------------------------------------------------------
// Helpers
// ---------------------------------------------------------------------------
__device__ __forceinline__ unsigned f2tf32(float x) {
    unsigned r;
    asm("cvt.rna.tf32.f32 %0, %1;" : "=r"(r) : "f"(x));
    return r;
}

__device__ __forceinline__ void mma_tf32(float4& d, const unsigned a[4],
                                         unsigned b0, unsigned b1) {
    asm volatile(
        "mma.sync.aligned.m16n8k8.row.col.f32.tf32.tf32.f32 "
        "{%0,%1,%2,%3}, {%4,%5,%6,%7}, {%8,%9}, {%0,%1,%2,%3};"
        : "+f"(d.x), "+f"(d.y), "+f"(d.z), "+f"(d.w)
        : "r"(a[0]), "r"(a[1]), "r"(a[2]), "r"(a[3]), "r"(b0), "r"(b1));
}

__device__ __forceinline__ void ldsm4(unsigned& r0, unsigned& r1,
                                      unsigned& r2, unsigned& r3,
                                      unsigned addr) {
    asm volatile(
        "ldmatrix.sync.aligned.m8n8.x4.shared.b16 {%0,%1,%2,%3}, [%4];"
        : "=r"(r0), "=r"(r1), "=r"(r2), "=r"(r3) : "r"(addr));
}

__device__ __forceinline__ void cp16(unsigned dst, const void* src) {
    asm volatile("cp.async.cg.shared.global [%0], [%1], 16;"
                 :: "r"(dst), "l"(src));
}
#define CP_COMMIT() asm volatile("cp.async.commit_group;" ::: "memory")
#define CP_WAIT0()  asm volatile("cp.async.wait_group 0;" ::: "memory")
#define CP_WAIT1()  asm volatile("cp.async.wait_group 1;" ::: "memory")

// exp2 on the FMA pipe (no MUFU): magic rounding + degree-4 poly.
__device__ __forceinline__ float fast_exp2(float z) {
    z = fmaxf(z, -126.0f);
    float kf = z + 12582912.0f;
    int   ki = __float_as_int(kf);
    float f  = z - (kf - 12582912.0f);
    float p  = 0.0096181291f;
    p = fmaf(p, f, 0.0555041087f);
    p = fmaf(p, f, 0.2402265070f);
    p = fmaf(p, f, 0.6931471806f);
    p = fmaf(p, f, 1.0f);
    return __int_as_float(__float_as_int(p) + (ki << 23));
}

// ---------------------------------------------------------------------------
// Elementwise fp32 -> tf32 convert (vectorized, grid-stride)
// ---------------------------------------------------------------------------
__global__ void cvt_tf32_kernel(const float4* __restrict__ s,
                                float4* __restrict__ d, int n4) {
    for (int i = blockIdx.x * blockDim.x + threadIdx.x; i < n4;
         i += gridDim.x * blockDim.x) {
        float4 v = s[i];
        uint4 u = {f2tf32(v.x), f2tf32(v.y), f2tf32(v.z), f2tf32(v.w)};
        ((uint4*)d)[i] = u;
    }
}

// ---------------------------------------------------------------------------
// Tensor-core GEMM (tf32, pre-converted operands):
//   C[m][n] = sum_k A[m][k]*B[n][k] + bias[n]
// 128x128 tile, BK=32, 8 warps (2m x 4n), 3-stage cp.async pipeline.
// EPI=1: A=g_xa, B=g_wqkv, scatter q/k (tf32) + v transposed
// EPI=2: A=g_attv, B=g_wout, plain fp32 write to C
// ---------------------------------------------------------------------------
#define GS          (128 * 36)
#define GEMM_SMEM_BYTES (6 * GS * 4)     // 3 stages * (A + B)

template <int EPI>
__global__ __launch_bounds__(256, 2) void gemm_tc(
    const float* __restrict__ bias, float* __restrict__ C, int N, int K)
{
    extern __shared__ float smg[];
    float* Asm = smg;            // [3][128][36]
    float* Bsm = smg + 3 * GS;   // [3][128][36]

    const float* Ap = (EPI == 2) ? g_attv : g_xa;
    const float* Bp = (EPI == 2) ? g_wout : g_wqkv;

    const int tid  = threadIdx.x;
    const int lane = tid & 31;
    const int wid  = tid >> 5;
    const int lr   = lane >> 2;
    const int lc   = lane & 3;
    const int wm   = (wid >> 2) * 64;
    const int wn   = (wid & 3) * 32;
    const int bm   = blockIdx.y * 128;
    const int bn   = blockIdx.x * 128;

    const int crow = tid >> 3;
    const int ck4  = (tid & 7) * 4;
    const float* aS = Ap + (size_t)(bm + crow) * K + ck4;
    const float* bS = Bp + (size_t)(bn + crow) * K + ck4;
    const unsigned aDst = (unsigned)__cvta_generic_to_shared(Asm) + (crow * 36 + ck4) * 4;
    const unsigned bDst = (unsigned)__cvta_generic_to_shared(Bsm) + (crow * 36 + ck4) * 4;

    const int rA = wm + (lane & 7) + ((lane >> 3) & 1) * 8;
    const int cA = ((lane >> 4) & 1) * 4;
    const int rB = wn + (lane & 7) + ((lane >> 4) & 1) * 8;
    const int cB = ((lane >> 3) & 1) * 4;
    const unsigned aBase = (unsigned)__cvta_generic_to_shared(Asm) + (rA * 36 + cA) * 4;
    const unsigned bBase = (unsigned)__cvta_generic_to_shared(Bsm) + (rB * 36 + cB) * 4;

    float4 acc[4][4];
#pragma unroll
    for (int i = 0; i < 4; ++i)
#pragma unroll
        for (int j = 0; j < 4; ++j) acc[i][j] = make_float4(0.f, 0.f, 0.f, 0.f);

    const int NKT = K / 32;

    auto issue = [&](int kt, int buf) {
        const unsigned so = buf * (GS * 4);
        const int ko = kt * 32;
#pragma unroll
        for (int it = 0; it < 4; ++it) {
            cp16(aDst + so + it * (32 * 36 * 4), aS + ko + (size_t)it * 32 * K);
            cp16(bDst + so + it * (32 * 36 * 4), bS + ko + (size_t)it * 32 * K);
        }
    };

    issue(0, 0); CP_COMMIT();
    issue(1, 1); CP_COMMIT();

    int curbuf = 0;
    for (int kt = 0; kt < NKT; ++kt) {
        if (kt + 1 < NKT) { CP_WAIT1(); } else { CP_WAIT0(); }
        __syncthreads();
        if (kt + 2 < NKT) {
            int nb = curbuf + 2; if (nb >= 3) nb -= 3;
            issue(kt + 2, nb);
            CP_COMMIT();
        }

        const unsigned stOff = curbuf * (GS * 4);
#pragma unroll
        for (int kk = 0; kk < 4; ++kk) {
            const unsigned kOff = stOff + kk * 8 * 4;
            unsigned af[4][4];
            unsigned bf[4][2];
#pragma unroll
            for (int i = 0; i < 4; ++i)
                ldsm4(af[i][0], af[i][1], af[i][2], af[i][3],
                      aBase + kOff + i * (16 * 36 * 4));
            ldsm4(bf[0][0], bf[0][1], bf[1][0], bf[1][1], bBase + kOff);
            ldsm4(bf[2][0], bf[2][1], bf[3][0], bf[3][1],
                  bBase + kOff + 16 * 36 * 4);
#pragma unroll
            for (int i = 0; i < 4; ++i)
#pragma unroll
                for (int j = 0; j < 4; ++j)
                    mma_tf32(acc[i][j], af[i], bf[j][0], bf[j][1]);
        }
        curbuf = (curbuf + 1 == 3) ? 0 : curbuf + 1;
    }

    // Epilogue
    const float QS = 0.125f * 1.4426950408889634f;
#pragma unroll
    for (int i = 0; i < 4; ++i) {
        int m0 = bm + wm + i * 16 + lr;
#pragma unroll
        for (int j = 0; j < 4; ++j) {
            int n0 = bn + wn + j * 8 + lc * 2;
            float bia0 = bias[n0], bia1 = bias[n0 + 1];
            float v00 = acc[i][j].x + bia0;
            float v01 = acc[i][j].y + bia1;
            float v10 = acc[i][j].z + bia0;
            float v11 = acc[i][j].w + bia1;
            if (EPI == 1) {
#pragma unroll
                for (int e = 0; e < 4; ++e) {
                    int m = m0 + ((e >> 1) ? 8 : 0);
                    int n = n0 + (e & 1);
                    float val = (e == 0) ? v00 : (e == 1) ? v01 : (e == 2) ? v10 : v11;
                    int b = m >> 11;
                    int t = m & 2047;
                    int h = n / 192;
                    int rr = n - h * 192;
                    int sel = rr >> 6;
                    int d = rr & 63;
                    if (sel == 0) {
                        size_t dst = (((size_t)(b * NH + h) * T_SEQ) + t) * HS + d;
                        g_q[dst] = __uint_as_float(f2tf32(val * QS));
                    } else if (sel == 1) {
                        size_t dst = (((size_t)(b * NH + h) * T_SEQ) + t) * HS + d;
                        g_k[dst] = __uint_as_float(f2tf32(val));
                    } else {
                        // V stored transposed: [b,h,d,t]
                        size_t dst = (((size_t)(b * NH + h) * HS) + d) * T_SEQ + t;
                        g_v[dst] = __uint_as_float(f2tf32(val));
                    }
                }
            } else {
                float2 r0 = {v00, v01};
                float2 r1 = {v10, v11};
                *(float2*)(C + (size_t)m0 * N + n0) = r0;
                *(float2*)(C + (size_t)(m0 + 8) * N + n0) = r1;
            }
        }
    }
}

// ---------------------------------------------------------------------------
// Flash attention, tf32 mma + LDSM feeds both phases + cp.async K/V.
// CTA: 128 q rows of one (b,h); 8 warps x 16 rows; 32 key chunks of 64.
// K natural [c][d] stride 68 (LDSM B-frags for QK^T).
// V transposed [d][c] stride 68 (LDSM B-frags for PV — symmetric with K).
// ---------------------------------------------------------------------------
#define PS 68
#define ATT_SMEM_BYTES ((128 * PS + 2 * 64 * PS + 2 * 64 * PS) * 4)

__global__ __launch_bounds__(256, 2) void attn_tc_kernel()
{
    extern __shared__ float sm[];
    float* Ps = sm;                        // [128][68]  Q staging, then P
    float* Ks = sm + 128 * PS;             // [2][64][68]  K [c][d]
    float* Vs = Ks + 2 * 64 * PS;          // [2][64][68]  V^T [d][c]

    const int bh = blockIdx.y;
    const int qb = blockIdx.x;
    const float* qp = g_q + ((size_t)bh * T_SEQ + (size_t)qb * 128) * HS;
    const float* kp = g_k + (size_t)bh * T_SEQ * HS;
    const float* vp = g_v + (size_t)bh * HS * T_SEQ;   // [d][t]

    const int tid  = threadIdx.x;
    const int lane = tid & 31;
    const int wid  = tid >> 5;
    const int lr   = lane >> 2;
    const int lc   = lane & 3;
    const int w16  = wid * 16;

    // cp.async mapping: row index cc+16*it, 4-elem col chunk cd0
    const int cc  = tid >> 4;
    const int cd0 = (tid & 15) * 4;
    const unsigned ksB = (unsigned)__cvta_generic_to_shared(Ks);
    const unsigned vsB = (unsigned)__cvta_generic_to_shared(Vs);

    // LDSM lane maps
    const int rA = (lane & 7) + ((lane >> 3) & 1) * 8;
    const int cA = ((lane >> 4) & 1) * 4;
    const int rB = (lane & 7) + ((lane >> 4) & 1) * 8;
    const int cB = ((lane >> 3) & 1) * 4;

    const unsigned pQ = (unsigned)__cvta_generic_to_shared(Ps) + ((w16 + rA) * PS + cA) * 4;
    const unsigned pK = ksB + (rB * PS + cB) * 4;
    const unsigned pV = vsB + (rB * PS + cB) * 4;

    auto issueKV = [&](int jc, int buf) {
        const float* kj = kp + (size_t)jc * 64 * HS;
        const float* vj = vp + (size_t)jc * 64;          // col offset in [d][t]
#pragma unroll
        for (int it = 0; it < 4; ++it) {
            int c = cc + it * 16;
            // K rows = keys, contiguous d
            cp16(ksB + ((buf * 64 + c) * PS + cd0) * 4, kj + c * HS + cd0);
            // V^T rows = d, contiguous t
            cp16(vsB + ((buf * 64 + c) * PS + cd0) * 4, vj + (size_t)c * T_SEQ + cd0);
        }
    };

    issueKV(0, 0);
    CP_COMMIT();

    // Stage Q (already tf32 + scaled)
#pragma unroll
    for (int it = 0; it < 8; ++it) {
        int slot = tid + it * 256;
        int r = slot >> 4;
        int d0 = (slot & 15) * 4;
        *(uint4*)(Ps + r * PS + d0) = *(const uint4*)(qp + r * HS + d0);
    }
    __syncthreads();

    unsigned qf[8][4];
#pragma unroll
    for (int kk = 0; kk < 8; ++kk)
        ldsm4(qf[kk][0], qf[kk][1], qf[kk][2], qf[kk][3], pQ + kk * 8 * 4);

    float4 o[8];
#pragma unroll
    for (int j = 0; j < 8; ++j) o[j] = make_float4(0.f, 0.f, 0.f, 0.f);
    float m0 = -1e30f, m1 = -1e30f, l0 = 0.f, l1 = 0.f;

    unsigned* pp = (unsigned*)Ps;

    for (int jc = 0; jc < T_SEQ / 64; ++jc) {
        const int cur = jc & 1;
        CP_WAIT0();
        __syncthreads();
        if (jc + 1 < T_SEQ / 64) { issueKV(jc + 1, cur ^ 1); CP_COMMIT(); }

        // S = Q K^T (warp 16x64)
        const unsigned pKc = pK + cur * (64 * PS * 4);
        float4 s[8];
#pragma unroll
        for (int j = 0; j < 8; ++j) s[j] = make_float4(0.f, 0.f, 0.f, 0.f);
#pragma unroll
        for (int kk = 0; kk < 8; ++kk) {
            const unsigned kOff = kk * 8 * 4;
            unsigned bf[8][2];
#pragma unroll
            for (int jp = 0; jp < 4; ++jp)
                ldsm4(bf[jp * 2][0], bf[jp * 2][1], bf[jp * 2 + 1][0], bf[jp * 2 + 1][1],
                      pKc + kOff + jp * (16 * PS * 4));
#pragma unroll
            for (int j = 0; j < 8; ++j)
                mma_tf32(s[j], qf[kk], bf[j][0], bf[j][1]);
        }

        // Online softmax (exp2 domain)
        float mx0 = -1e30f, mx1 = -1e30f;
#pragma unroll
        for (int j = 0; j < 8; ++j) {
            mx0 = fmaxf(mx0, fmaxf(s[j].x, s[j].y));
            mx1 = fmaxf(mx1, fmaxf(s[j].z, s[j].w));
        }
        mx0 = fmaxf(mx0, __shfl_xor_sync(0xffffffffu, mx0, 1));
        mx0 = fmaxf(mx0, __shfl_xor_sync(0xffffffffu, mx0, 2));
        mx1 = fmaxf(mx1, __shfl_xor_sync(0xffffffffu, mx1, 1));
        mx1 = fmaxf(mx1, __shfl_xor_sync(0xffffffffu, mx1, 2));
        float mn0 = fmaxf(m0, mx0);
        float mn1 = fmaxf(m1, mx1);
        float a0 = fast_exp2(m0 - mn0);
        float a1 = fast_exp2(m1 - mn1);
        m0 = mn0; m1 = mn1;

        float s0 = 0.f, s1 = 0.f;
        const int row0 = (w16 + lr) * PS;
        const int row1 = (w16 + lr + 8) * PS;
#pragma unroll
        for (int j = 0; j < 8; ++j) {
            float px = fast_exp2(s[j].x - mn0);
            float py = fast_exp2(s[j].y - mn0);
            float pz = fast_exp2(s[j].z - mn1);
            float pw = fast_exp2(s[j].w - mn1);
            s0 += px + py;
            s1 += pz + pw;
            int cix = j * 8 + lc * 2;
            uint2 u0 = {f2tf32(px), f2tf32(py)};
            uint2 u1 = {f2tf32(pz), f2tf32(pw)};
            *(uint2*)&pp[row0 + cix] = u0;
            *(uint2*)&pp[row1 + cix] = u1;
        }
        s0 += __shfl_xor_sync(0xffffffffu, s0, 1);
        s0 += __shfl_xor_sync(0xffffffffu, s0, 2);
        s1 += __shfl_xor_sync(0xffffffffu, s1, 1);
        s1 += __shfl_xor_sync(0xffffffffu, s1, 2);
        l0 = l0 * a0 + s0;
        l1 = l1 * a1 + s1;
#pragma unroll
        for (int j = 0; j < 8; ++j) {
            o[j].x *= a0; o[j].y *= a0;
            o[j].z *= a1; o[j].w *= a1;
        }
        __syncwarp();   // P rows warp-private

        // O += P V : A-frags = P (LDSM), B-frags = V^T (LDSM, symmetric w/ K)
        const unsigned pVc = pV + cur * (64 * PS * 4);
#pragma unroll
        for (int kk = 0; kk < 8; ++kk) {
            const unsigned kOff = kk * 8 * 4;
            unsigned af[4];
            ldsm4(af[0], af[1], af[2], af[3], pQ + kOff);
            unsigned bf[8][2];
#pragma unroll
            for (int jp = 0; jp < 4; ++jp)
                ldsm4(bf[jp * 2][0], bf[jp * 2][1], bf[jp * 2 + 1][0], bf[jp * 2 + 1][1],
                      pVc + kOff + jp * (16 * PS * 4));
#pragma unroll
            for (int j = 0; j < 8; ++j)
                mma_tf32(o[j], af, bf[j][0], bf[j][1]);
        }
    }

    // Epilogue: normalize, emit tf32 into g_attv
    float inv0 = 1.0f / l0;
    float inv1 = 1.0f / l1;
    const int b = bh >> 4;
    const int h = bh & 15;
    const int t0 = qb * 128 + w16 + lr;
#pragma unroll
    for (int j = 0; j < 8; ++j) {
        int col = h * 64 + j * 8 + lc * 2;
        uint2 r0 = {f2tf32(o[j].x * inv0), f2tf32(o[j].y * inv0)};
        uint2 r1 = {f2tf32(o[j].z * inv1), f2tf32(o[j].w * inv1)};
        *(uint2*)(g_attv + (size_t)(b * T_SEQ + t0) * CDIM + col) = r0;
        *(uint2*)(g_attv + (size_t)(b * T_SEQ + t0 + 8) * CDIM + col) = r1;
    }
}

// ---------------------------------------------------------------------------
extern "C" void kernel_launch(void* const* d_in, const int* in_sizes, int n_in,
                              void* d_out, int out_size)
{
    const float* x    = (const float*)d_in[0];
    const float* Wqkv = (const float*)d_in[1];
    const float* bqkv = (const float*)d_in[2];
    const float* Wout = (const float*)d_in[3];
    const float* bout = (const float*)d_in[4];
    float* out = (float*)d_out;

    cudaFuncSetAttribute(gemm_tc<1>, cudaFuncAttributeMaxDynamicSharedMemorySize, GEMM_SMEM_BYTES);
    cudaFuncSetAttribute(gemm_tc<2>, cudaFuncAttributeMaxDynamicSharedMemorySize, GEMM_SMEM_BYTES);
    cudaFuncSetAttribute(attn_tc_kernel, cudaFuncAttributeMaxDynamicSharedMemorySize, ATT_SMEM_BYTES);

    float* d_xa;   cudaGetSymbolAddress((void**)&d_xa,   g_xa);
    float* d_wq;   cudaGetSymbolAddress((void**)&d_wq,   g_wqkv);
    float* d_wo;   cudaGetSymbolAddress((void**)&d_wo,   g_wout);

    // Pre-convert operands to tf32 (RNA)
    cvt_tf32_kernel<<<592, 256>>>((const float4*)x,    (float4*)d_xa, MROWS * CDIM / 4);
    cvt_tf32_kernel<<<592, 256>>>((const float4*)Wqkv, (float4*)d_wq, 3 * CDIM * CDIM / 4);
    cvt_tf32_kernel<<<592, 256>>>((const float4*)Wout, (float4*)d_wo, CDIM * CDIM / 4);

    // QKV projection: M=8192, N=3072, K=1024 -> q/k natural, v transposed
    gemm_tc<1><<<dim3(3072 / 128, MROWS / 128), 256, GEMM_SMEM_BYTES>>>(
        bqkv, nullptr, 3 * CDIM, CDIM);

    // Attention
    attn_tc_kernel<<<dim3(T_SEQ / 128, BATCH * NH), 256, ATT_SMEM_BYTES>>>();

    // Output projection: M=8192, N=1024, K=1024
    gemm_tc<2><<<dim3(CDIM / 128, MROWS / 128), 256, GEMM_SMEM_BYTES>>>(
        bout, out, CDIM, CDIM);
}

// round 7
// speedup vs baseline: 1.8073x; 1.8073x over previous
#include <cuda_runtime.h>
#include <cuda_fp16.h>
#include <cstdint>

// ---------------------------------------------------------------------------
// MultiHeadAttention: B=4, T=2048, C=1024, H=16, hs=64 (fp32 I/O)
// Round 7: all matmuls on mma.sync m16n8k16 fp16 (same 10-bit mantissa as
// tf32, 2x K per instruction). Pre-converted fp16 operands, LDSM feeds,
// cp.async double-buffered staging, FMA-pipe exp2 softmax.
// ---------------------------------------------------------------------------

#define BATCH   4
#define T_SEQ   2048
#define NH      16
#define HS      64
#define CDIM    1024
#define MROWS   (BATCH * T_SEQ)          // 8192

// Scratch (device globals), fp16.
__device__ __half g_xa[MROWS * CDIM];
__device__ __half g_wqkv[3 * CDIM * CDIM];
__device__ __half g_wout[CDIM * CDIM];
__device__ __half g_q[BATCH * NH * T_SEQ * HS];     // [b,h,t,d], pre-scaled
__device__ __half g_k[BATCH * NH * T_SEQ * HS];     // [b,h,t,d]
__device__ __half g_v[BATCH * NH * HS * T_SEQ];     // [b,h,d,t] (transposed)
__device__ __half g_attv[BATCH * T_SEQ * CDIM];     // [b,t,h*hs+d]

// ---------------------------------------------------------------------------
// Helpers
// ---------------------------------------------------------------------------
__device__ __forceinline__ void mma_f16(float4& d, const unsigned a[4],
                                        unsigned b0, unsigned b1) {
    asm volatile(
        "mma.sync.aligned.m16n8k16.row.col.f32.f16.f16.f32 "
        "{%0,%1,%2,%3}, {%4,%5,%6,%7}, {%8,%9}, {%0,%1,%2,%3};"
        : "+f"(d.x), "+f"(d.y), "+f"(d.z), "+f"(d.w)
        : "r"(a[0]), "r"(a[1]), "r"(a[2]), "r"(a[3]), "r"(b0), "r"(b1));
}

__device__ __forceinline__ void ldsm4(unsigned& r0, unsigned& r1,
                                      unsigned& r2, unsigned& r3,
                                      unsigned addr) {
    asm volatile(
        "ldmatrix.sync.aligned.m8n8.x4.shared.b16 {%0,%1,%2,%3}, [%4];"
        : "=r"(r0), "=r"(r1), "=r"(r2), "=r"(r3) : "r"(addr));
}

__device__ __forceinline__ void cp16(unsigned dst, const void* src) {
    asm volatile("cp.async.cg.shared.global [%0], [%1], 16;"
                 :: "r"(dst), "l"(src));
}
#define CP_COMMIT() asm volatile("cp.async.commit_group;" ::: "memory")
#define CP_WAIT0()  asm volatile("cp.async.wait_group 0;" ::: "memory")

__device__ __forceinline__ unsigned h2u(__half2 h) {
    return *(unsigned*)&h;
}

// exp2 on the FMA pipe (no MUFU): magic rounding + degree-4 poly.
__device__ __forceinline__ float fast_exp2(float z) {
    z = fmaxf(z, -126.0f);
    float kf = z + 12582912.0f;
    int   ki = __float_as_int(kf);
    float f  = z - (kf - 12582912.0f);
    float p  = 0.0096181291f;
    p = fmaf(p, f, 0.0555041087f);
    p = fmaf(p, f, 0.2402265070f);
    p = fmaf(p, f, 0.6931471806f);
    p = fmaf(p, f, 1.0f);
    return __int_as_float(__float_as_int(p) + (ki << 23));
}

// ---------------------------------------------------------------------------
// Elementwise fp32 -> fp16 convert (8 elems/thread/iter)
// ---------------------------------------------------------------------------
__global__ void cvt_f16_kernel(const float4* __restrict__ s,
                               uint4* __restrict__ d, int n8) {
    for (int i = blockIdx.x * blockDim.x + threadIdx.x; i < n8;
         i += gridDim.x * blockDim.x) {
        float4 a = s[2 * i], b = s[2 * i + 1];
        uint4 u;
        u.x = h2u(__floats2half2_rn(a.x, a.y));
        u.y = h2u(__floats2half2_rn(a.z, a.w));
        u.z = h2u(__floats2half2_rn(b.x, b.y));
        u.w = h2u(__floats2half2_rn(b.z, b.w));
        d[i] = u;
    }
}

// ---------------------------------------------------------------------------
// fp16 tensor-core GEMM: C[m][n] = sum_k A[m][k]*B[n][k] + bias[n]
// 128x128 tile, BK=64 halves (128B row), 8 warps (2m x 4n), warp tile 64x32,
// double-buffered cp.async. Row stride 144B => LDSM conflict-free.
// EPI=1: A=g_xa, B=g_wqkv -> scatter q (scaled fp16) / k / v^T
// EPI=2: A=g_attv, B=g_wout -> fp32 C
// ---------------------------------------------------------------------------
#define ROWB 144                          // smem row stride (bytes)
#define GS_B (128 * ROWB)                 // one tile (bytes)
#define GEMM_SMEM_BYTES (4 * GS_B)        // 2 stages * (A + B)
#define GM_K 1024
#define GM_NKT (GM_K / 64)                // 16

template <int EPI>
__global__ __launch_bounds__(256, 2) void gemm_f16(
    const float* __restrict__ bias, float* __restrict__ C, int N)
{
    extern __shared__ char smg[];
    const unsigned aSt = (unsigned)__cvta_generic_to_shared(smg);
    const unsigned bSt = aSt + 2 * GS_B;

    const __half* Ap = (EPI == 2) ? g_attv : g_xa;
    const __half* Bp = (EPI == 2) ? g_wout : g_wqkv;

    const int tid  = threadIdx.x;
    const int lane = tid & 31;
    const int wid  = tid >> 5;
    const int lr   = lane >> 2;
    const int lc   = lane & 3;
    const int wm   = (wid >> 2) * 64;
    const int wn   = (wid & 3) * 32;
    const int bm   = blockIdx.y * 128;
    const int bn   = blockIdx.x * 128;

    // cp.async mapping: 4 chunks of 16B per matrix per thread
    unsigned sOff[4]; size_t gOffH[4];
#pragma unroll
    for (int i = 0; i < 4; ++i) {
        int u = tid + i * 256;          // 0..1023
        int row = u >> 3;               // 0..127
        int ch  = u & 7;                // 16B chunk in 128B row
        sOff[i]  = (unsigned)(row * ROWB + ch * 16);
        gOffH[i] = (size_t)row * GM_K + ch * 8;      // halves
    }
    const __half* aG = Ap + (size_t)bm * GM_K;
    const __half* bG = Bp + (size_t)bn * GM_K;

    // LDSM lane maps (byte offsets; 16B = 8 halves = one k-octet)
    const int rA = wm + (lane & 7) + ((lane >> 3) & 1) * 8;
    const unsigned cA = ((lane >> 4) & 1) * 16;
    const int rB = wn + (lane & 7) + ((lane >> 4) & 1) * 8;
    const unsigned cB = ((lane >> 3) & 1) * 16;
    const unsigned aBase = aSt + rA * ROWB + cA;
    const unsigned bBase = bSt + rB * ROWB + cB;

    float4 acc[4][4];
#pragma unroll
    for (int i = 0; i < 4; ++i)
#pragma unroll
        for (int j = 0; j < 4; ++j) acc[i][j] = make_float4(0.f, 0.f, 0.f, 0.f);

    auto issue = [&](int kt, int buf) {
        const unsigned so = buf * GS_B;
        const size_t ko = (size_t)kt * 64;   // halves
#pragma unroll
        for (int i = 0; i < 4; ++i) {
            cp16(aSt + so + sOff[i], aG + gOffH[i] + ko);
            cp16(bSt + so + sOff[i], bG + gOffH[i] + ko);
        }
    };

    issue(0, 0);
    CP_COMMIT();

    for (int kt = 0; kt < GM_NKT; ++kt) {
        const int cur = kt & 1;
        CP_WAIT0();
        __syncthreads();
        if (kt + 1 < GM_NKT) { issue(kt + 1, cur ^ 1); CP_COMMIT(); }

        const unsigned stOff = cur * GS_B;
#pragma unroll
        for (int kk = 0; kk < 4; ++kk) {            // k16 steps over BK=64
            const unsigned kOff = stOff + kk * 32;  // 16 halves = 32B
            unsigned af[4][4];
            unsigned bf[4][2];
#pragma unroll
            for (int i = 0; i < 4; ++i)
                ldsm4(af[i][0], af[i][1], af[i][2], af[i][3],
                      aBase + kOff + i * (16 * ROWB));
            ldsm4(bf[0][0], bf[0][1], bf[1][0], bf[1][1], bBase + kOff);
            ldsm4(bf[2][0], bf[2][1], bf[3][0], bf[3][1],
                  bBase + kOff + 16 * ROWB);
#pragma unroll
            for (int i = 0; i < 4; ++i)
#pragma unroll
                for (int j = 0; j < 4; ++j)
                    mma_f16(acc[i][j], af[i], bf[j][0], bf[j][1]);
        }
    }

    // Epilogue
    const float QS = 0.125f * 1.4426950408889634f;
#pragma unroll
    for (int i = 0; i < 4; ++i) {
        int m0 = bm + wm + i * 16 + lr;              // rows m0, m0+8
#pragma unroll
        for (int j = 0; j < 4; ++j) {
            int n0 = bn + wn + j * 8 + lc * 2;       // cols n0, n0+1 (even)
            float bia0 = bias[n0], bia1 = bias[n0 + 1];
            float v00 = acc[i][j].x + bia0;
            float v01 = acc[i][j].y + bia1;
            float v10 = acc[i][j].z + bia0;
            float v11 = acc[i][j].w + bia1;
            if (EPI == 1) {
                int b = m0 >> 11;
                int t = m0 & 2047;
                int h = n0 / 192;
                int rr = n0 - h * 192;
                int sel = rr >> 6;
                int d = rr & 63;                     // d, d+1 in same block
                if (sel == 0) {
                    __half* dst = g_q + (((size_t)(b * NH + h) * T_SEQ) + t) * HS + d;
                    *(__half2*)dst            = __floats2half2_rn(v00 * QS, v01 * QS);
                    *(__half2*)(dst + 8 * HS) = __floats2half2_rn(v10 * QS, v11 * QS);
                } else if (sel == 1) {
                    __half* dst = g_k + (((size_t)(b * NH + h) * T_SEQ) + t) * HS + d;
                    *(__half2*)dst            = __floats2half2_rn(v00, v01);
                    *(__half2*)(dst + 8 * HS) = __floats2half2_rn(v10, v11);
                } else {
                    // V transposed [b,h,d,t]
                    __half* vb = g_v + ((size_t)(b * NH + h) * HS + d) * T_SEQ + t;
                    vb[0]             = __float2half_rn(v00);
                    vb[T_SEQ]         = __float2half_rn(v01);
                    vb[8]             = __float2half_rn(v10);
                    vb[T_SEQ + 8]     = __float2half_rn(v11);
                }
            } else {
                float2 r0 = {v00, v01};
                float2 r1 = {v10, v11};
                *(float2*)(C + (size_t)m0 * N + n0) = r0;
                *(float2*)(C + (size_t)(m0 + 8) * N + n0) = r1;
            }
        }
    }
}

// ---------------------------------------------------------------------------
// Flash attention, fp16 mma m16n8k16 + LDSM + cp.async double-buffered K/V.
// CTA: 128 q rows of one (b,h); 8 warps x 16 rows; 32 key chunks of 64.
// K natural [c][d], V^T [d][c], P [r][c] — all stride 72 halves (144B).
// ---------------------------------------------------------------------------
#define KVB (64 * ROWB)                  // one K or V buffer (bytes)
#define ATT_SMEM_BYTES (128 * ROWB + 4 * KVB)

__global__ __launch_bounds__(256, 2) void attn_f16_kernel()
{
    extern __shared__ char sma[];
    const unsigned psA = (unsigned)__cvta_generic_to_shared(sma);
    const unsigned ksA = psA + 128 * ROWB;
    const unsigned vsA = ksA + 2 * KVB;
    __half* PsH = (__half*)sma;

    const int bh = blockIdx.y;
    const int qb = blockIdx.x;
    const __half* qp = g_q + ((size_t)bh * T_SEQ + (size_t)qb * 128) * HS;
    const __half* kp = g_k + (size_t)bh * T_SEQ * HS;
    const __half* vp = g_v + (size_t)bh * HS * T_SEQ;   // [d][t]

    const int tid  = threadIdx.x;
    const int lane = tid & 31;
    const int wid  = tid >> 5;
    const int lr   = lane >> 2;
    const int lc   = lane & 3;
    const int w16  = wid * 16;

    // LDSM lane maps
    const int rA = (lane & 7) + ((lane >> 3) & 1) * 8;
    const unsigned cA = ((lane >> 4) & 1) * 16;
    const int rB = (lane & 7) + ((lane >> 4) & 1) * 8;
    const unsigned cB = ((lane >> 3) & 1) * 16;

    const unsigned pQ = psA + (w16 + rA) * ROWB + cA;   // A frags (Q, P)
    const unsigned pK = ksA + rB * ROWB + cB;
    const unsigned pV = vsA + rB * ROWB + cB;

    auto issueKV = [&](int jc, int buf) {
        const __half* kj = kp + (size_t)jc * 64 * HS;
        const __half* vj = vp + (size_t)jc * 64;
#pragma unroll
        for (int it = 0; it < 2; ++it) {
            int u = tid + it * 256;          // 0..511
            int row = u >> 3;                // 0..63
            int ch  = u & 7;
            unsigned so = buf * KVB + row * ROWB + ch * 16;
            cp16(ksA + so, kj + (size_t)row * HS + ch * 8);
            cp16(vsA + so, vj + (size_t)row * T_SEQ + ch * 8);
        }
    };

    issueKV(0, 0);
    CP_COMMIT();

    // Stage Q (already fp16 + scaled): 128 rows x 64 halves
#pragma unroll
    for (int it = 0; it < 4; ++it) {
        int u = tid + it * 256;              // 0..1023
        int row = u >> 3;
        int ch  = u & 7;
        *(uint4*)(sma + row * ROWB + ch * 16) =
            *(const uint4*)(qp + (size_t)row * HS + ch * 8);
    }
    __syncthreads();

    unsigned qf[4][4];
#pragma unroll
    for (int kk = 0; kk < 4; ++kk)
        ldsm4(qf[kk][0], qf[kk][1], qf[kk][2], qf[kk][3], pQ + kk * 32);

    float4 o[8];
#pragma unroll
    for (int j = 0; j < 8; ++j) o[j] = make_float4(0.f, 0.f, 0.f, 0.f);
    float m0 = -1e30f, m1 = -1e30f, l0 = 0.f, l1 = 0.f;

    for (int jc = 0; jc < T_SEQ / 64; ++jc) {
        const int cur = jc & 1;
        CP_WAIT0();
        __syncthreads();
        if (jc + 1 < T_SEQ / 64) { issueKV(jc + 1, cur ^ 1); CP_COMMIT(); }

        // S = Q K^T (warp 16x64), kk = 4 steps of k16
        const unsigned pKc = pK + cur * KVB;
        float4 s[8];
#pragma unroll
        for (int j = 0; j < 8; ++j) s[j] = make_float4(0.f, 0.f, 0.f, 0.f);
#pragma unroll
        for (int kk = 0; kk < 4; ++kk) {
            const unsigned kOff = kk * 32;
            unsigned bf[8][2];
#pragma unroll
            for (int jp = 0; jp < 4; ++jp)
                ldsm4(bf[jp * 2][0], bf[jp * 2][1],
                      bf[jp * 2 + 1][0], bf[jp * 2 + 1][1],
                      pKc + kOff + jp * (16 * ROWB));
#pragma unroll
            for (int j = 0; j < 8; ++j)
                mma_f16(s[j], qf[kk], bf[j][0], bf[j][1]);
        }

        // Online softmax (exp2 domain)
        float mx0 = -1e30f, mx1 = -1e30f;
#pragma unroll
        for (int j = 0; j < 8; ++j) {
            mx0 = fmaxf(mx0, fmaxf(s[j].x, s[j].y));
            mx1 = fmaxf(mx1, fmaxf(s[j].z, s[j].w));
        }
        mx0 = fmaxf(mx0, __shfl_xor_sync(0xffffffffu, mx0, 1));
        mx0 = fmaxf(mx0, __shfl_xor_sync(0xffffffffu, mx0, 2));
        mx1 = fmaxf(mx1, __shfl_xor_sync(0xffffffffu, mx1, 1));
        mx1 = fmaxf(mx1, __shfl_xor_sync(0xffffffffu, mx1, 2));
        float mn0 = fmaxf(m0, mx0);
        float mn1 = fmaxf(m1, mx1);
        float a0 = fast_exp2(m0 - mn0);
        float a1 = fast_exp2(m1 - mn1);
        m0 = mn0; m1 = mn1;

        float s0 = 0.f, s1 = 0.f;
        const int row0 = (w16 + lr) * 72;      // halves
        const int row1 = (w16 + lr + 8) * 72;
#pragma unroll
        for (int j = 0; j < 8; ++j) {
            float px = fast_exp2(s[j].x - mn0);
            float py = fast_exp2(s[j].y - mn0);
            float pz = fast_exp2(s[j].z - mn1);
            float pw = fast_exp2(s[j].w - mn1);
            s0 += px + py;
            s1 += pz + pw;
            int cix = j * 8 + lc * 2;
            *(__half2*)&PsH[row0 + cix] = __floats2half2_rn(px, py);
            *(__half2*)&PsH[row1 + cix] = __floats2half2_rn(pz, pw);
        }
        s0 += __shfl_xor_sync(0xffffffffu, s0, 1);
        s0 += __shfl_xor_sync(0xffffffffu, s0, 2);
        s1 += __shfl_xor_sync(0xffffffffu, s1, 1);
        s1 += __shfl_xor_sync(0xffffffffu, s1, 2);
        l0 = l0 * a0 + s0;
        l1 = l1 * a1 + s1;
#pragma unroll
        for (int j = 0; j < 8; ++j) {
            o[j].x *= a0; o[j].y *= a0;
            o[j].z *= a1; o[j].w *= a1;
        }
        __syncwarp();     // P rows warp-private

        // O += P V : A frags = P (LDSM), B frags = V^T (LDSM)
        const unsigned pVc = pV + cur * KVB;
#pragma unroll
        for (int kk = 0; kk < 4; ++kk) {       // k16 over 64 keys
            const unsigned kOff = kk * 32;
            unsigned af[4];
            ldsm4(af[0], af[1], af[2], af[3], pQ + kOff);
            unsigned bf[8][2];
#pragma unroll
            for (int jp = 0; jp < 4; ++jp)
                ldsm4(bf[jp * 2][0], bf[jp * 2][1],
                      bf[jp * 2 + 1][0], bf[jp * 2 + 1][1],
                      pVc + kOff + jp * (16 * ROWB));
#pragma unroll
            for (int j = 0; j < 8; ++j)
                mma_f16(o[j], af, bf[j][0], bf[j][1]);
        }
    }

    // Epilogue: normalize, emit fp16 into g_attv
    float inv0 = 1.0f / l0;
    float inv1 = 1.0f / l1;
    const int b = bh >> 4;
    const int h = bh & 15;
    const int t0 = qb * 128 + w16 + lr;
#pragma unroll
    for (int j = 0; j < 8; ++j) {
        int col = h * 64 + j * 8 + lc * 2;
        *(__half2*)(g_attv + (size_t)(b * T_SEQ + t0) * CDIM + col) =
            __floats2half2_rn(o[j].x * inv0, o[j].y * inv0);
        *(__half2*)(g_attv + (size_t)(b * T_SEQ + t0 + 8) * CDIM + col) =
            __floats2half2_rn(o[j].z * inv1, o[j].w * inv1);
    }
}

// ---------------------------------------------------------------------------
extern "C" void kernel_launch(void* const* d_in, const int* in_sizes, int n_in,
                              void* d_out, int out_size)
{
    const float* x    = (const float*)d_in[0];
    const float* Wqkv = (const float*)d_in[1];
    const float* bqkv = (const float*)d_in[2];
    const float* Wout = (const float*)d_in[3];
    const float* bout = (const float*)d_in[4];
    float* out = (float*)d_out;

    cudaFuncSetAttribute(gemm_f16<1>, cudaFuncAttributeMaxDynamicSharedMemorySize, GEMM_SMEM_BYTES);
    cudaFuncSetAttribute(gemm_f16<2>, cudaFuncAttributeMaxDynamicSharedMemorySize, GEMM_SMEM_BYTES);
    cudaFuncSetAttribute(attn_f16_kernel, cudaFuncAttributeMaxDynamicSharedMemorySize, ATT_SMEM_BYTES);

    __half* d_xa;  cudaGetSymbolAddress((void**)&d_xa, g_xa);
    __half* d_wq;  cudaGetSymbolAddress((void**)&d_wq, g_wqkv);
    __half* d_wo;  cudaGetSymbolAddress((void**)&d_wo, g_wout);

    // Pre-convert operands to fp16 (RN)
    cvt_f16_kernel<<<592, 256>>>((const float4*)x,    (uint4*)d_xa, MROWS * CDIM / 8);
    cvt_f16_kernel<<<592, 256>>>((const float4*)Wqkv, (uint4*)d_wq, 3 * CDIM * CDIM / 8);
    cvt_f16_kernel<<<592, 256>>>((const float4*)Wout, (uint4*)d_wo, CDIM * CDIM / 8);

    // QKV projection: M=8192, N=3072, K=1024 -> q/k natural, v transposed
    gemm_f16<1><<<dim3(3072 / 128, MROWS / 128), 256, GEMM_SMEM_BYTES>>>(
        bqkv, nullptr, 3 * CDIM);

    // Attention
    attn_f16_kernel<<<dim3(T_SEQ / 128, BATCH * NH), 256, ATT_SMEM_BYTES>>>();

    // Output projection: M=8192, N=1024, K=1024
    gemm_f16<2><<<dim3(CDIM / 128, MROWS / 128), 256, GEMM_SMEM_BYTES>>>(
        bout, out, CDIM);
}

// round 8
// speedup vs baseline: 2.0662x; 1.1432x over previous
#include <cuda_runtime.h>
#include <cuda_fp16.h>
#include <cstdint>

// ---------------------------------------------------------------------------
// MultiHeadAttention: B=4, T=2048, C=1024, H=16, hs=64 (fp32 I/O)
// Round 8: smem-traffic-optimized fp16 mma.sync. 4 fat warps per CTA
// (64x64 warp tiles), P kept in registers (fragment identity), MUFU exp2.
// ---------------------------------------------------------------------------

#define BATCH   4
#define T_SEQ   2048
#define NH      16
#define HS      64
#define CDIM    1024
#define MROWS   (BATCH * T_SEQ)          // 8192

// Scratch (device globals), fp16.
__device__ __half g_xa[MROWS * CDIM];
__device__ __half g_wqkv[3 * CDIM * CDIM];
__device__ __half g_wout[CDIM * CDIM];
__device__ __half g_q[BATCH * NH * T_SEQ * HS];     // [b,h,t,d], pre-scaled
__device__ __half g_k[BATCH * NH * T_SEQ * HS];     // [b,h,t,d]
__device__ __half g_v[BATCH * NH * HS * T_SEQ];     // [b,h,d,t] (transposed)
__device__ __half g_attv[BATCH * T_SEQ * CDIM];     // [b,t,h*hs+d]

// ---------------------------------------------------------------------------
// Helpers
// ---------------------------------------------------------------------------
__device__ __forceinline__ void mma_f16(float4& d, const unsigned a[4],
                                        unsigned b0, unsigned b1) {
    asm volatile(
        "mma.sync.aligned.m16n8k16.row.col.f32.f16.f16.f32 "
        "{%0,%1,%2,%3}, {%4,%5,%6,%7}, {%8,%9}, {%0,%1,%2,%3};"
        : "+f"(d.x), "+f"(d.y), "+f"(d.z), "+f"(d.w)
        : "r"(a[0]), "r"(a[1]), "r"(a[2]), "r"(a[3]), "r"(b0), "r"(b1));
}

__device__ __forceinline__ void ldsm4(unsigned& r0, unsigned& r1,
                                      unsigned& r2, unsigned& r3,
                                      unsigned addr) {
    asm volatile(
        "ldmatrix.sync.aligned.m8n8.x4.shared.b16 {%0,%1,%2,%3}, [%4];"
        : "=r"(r0), "=r"(r1), "=r"(r2), "=r"(r3) : "r"(addr));
}

__device__ __forceinline__ void cp16(unsigned dst, const void* src) {
    asm volatile("cp.async.cg.shared.global [%0], [%1], 16;"
                 :: "r"(dst), "l"(src));
}
#define CP_COMMIT() asm volatile("cp.async.commit_group;" ::: "memory")
#define CP_WAIT0()  asm volatile("cp.async.wait_group 0;" ::: "memory")

__device__ __forceinline__ unsigned h2u(__half2 h) { return *(unsigned*)&h; }

__device__ __forceinline__ float ex2f(float x) {
    float r;
    asm("ex2.approx.f32 %0, %1;" : "=f"(r) : "f"(x));
    return r;
}

// ---------------------------------------------------------------------------
// Elementwise fp32 -> fp16 convert (8 elems/thread/iter)
// ---------------------------------------------------------------------------
__global__ void cvt_f16_kernel(const float4* __restrict__ s,
                               uint4* __restrict__ d, int n8) {
    for (int i = blockIdx.x * blockDim.x + threadIdx.x; i < n8;
         i += gridDim.x * blockDim.x) {
        float4 a = s[2 * i], b = s[2 * i + 1];
        uint4 u;
        u.x = h2u(__floats2half2_rn(a.x, a.y));
        u.y = h2u(__floats2half2_rn(a.z, a.w));
        u.z = h2u(__floats2half2_rn(b.x, b.y));
        u.w = h2u(__floats2half2_rn(b.z, b.w));
        d[i] = u;
    }
}

// ---------------------------------------------------------------------------
// fp16 GEMM: C[m][n] = sum_k A[m][k]*B[n][k] + bias[n]
// 128x128 CTA tile, BK=64 halves, 4 warps (2m x 2n), warp tile 64x64,
// double-buffered cp.async. Row stride 144B => LDSM conflict-free.
// ---------------------------------------------------------------------------
#define ROWB 144
#define GS_B (128 * ROWB)
#define GEMM_SMEM_BYTES (4 * GS_B)       // 2 stages * (A + B)
#define GM_K 1024
#define GM_NKT (GM_K / 64)               // 16

template <int EPI>
__global__ __launch_bounds__(128, 2) void gemm_f16(
    const float* __restrict__ bias, float* __restrict__ C, int N)
{
    extern __shared__ char smg[];
    const unsigned aSt = (unsigned)__cvta_generic_to_shared(smg);
    const unsigned bSt = aSt + 2 * GS_B;

    const __half* Ap = (EPI == 2) ? g_attv : g_xa;
    const __half* Bp = (EPI == 2) ? g_wout : g_wqkv;

    const int tid  = threadIdx.x;
    const int lane = tid & 31;
    const int wid  = tid >> 5;           // 0..3
    const int lr   = lane >> 2;
    const int lc   = lane & 3;
    const int wm   = (wid >> 1) * 64;
    const int wn   = (wid & 1) * 64;
    const int bm   = blockIdx.y * 128;
    const int bn   = blockIdx.x * 128;

    // cp.async mapping: 8 chunks of 16B per matrix per thread
    unsigned sOff[8]; size_t gOffH[8];
#pragma unroll
    for (int i = 0; i < 8; ++i) {
        int u = tid + i * 128;           // 0..1023
        int row = u >> 3;                // 0..127
        int ch  = u & 7;
        sOff[i]  = (unsigned)(row * ROWB + ch * 16);
        gOffH[i] = (size_t)row * GM_K + ch * 8;
    }
    const __half* aG = Ap + (size_t)bm * GM_K;
    const __half* bG = Bp + (size_t)bn * GM_K;

    // LDSM lane maps
    const int rA = wm + (lane & 7) + ((lane >> 3) & 1) * 8;
    const unsigned cA = ((lane >> 4) & 1) * 16;
    const int rB = wn + (lane & 7) + ((lane >> 4) & 1) * 8;
    const unsigned cB = ((lane >> 3) & 1) * 16;
    const unsigned aBase = aSt + rA * ROWB + cA;
    const unsigned bBase = bSt + rB * ROWB + cB;

    float4 acc[4][8];
#pragma unroll
    for (int i = 0; i < 4; ++i)
#pragma unroll
        for (int j = 0; j < 8; ++j) acc[i][j] = make_float4(0.f, 0.f, 0.f, 0.f);

    auto issue = [&](int kt, int buf) {
        const unsigned so = buf * GS_B;
        const size_t ko = (size_t)kt * 64;
#pragma unroll
        for (int i = 0; i < 8; ++i) {
            cp16(aSt + so + sOff[i], aG + gOffH[i] + ko);
            cp16(bSt + so + sOff[i], bG + gOffH[i] + ko);
        }
    };

    issue(0, 0);
    CP_COMMIT();

    for (int kt = 0; kt < GM_NKT; ++kt) {
        const int cur = kt & 1;
        CP_WAIT0();
        __syncthreads();
        if (kt + 1 < GM_NKT) { issue(kt + 1, cur ^ 1); CP_COMMIT(); }

        const unsigned stOff = cur * GS_B;
#pragma unroll
        for (int kk = 0; kk < 4; ++kk) {
            const unsigned kOff = stOff + kk * 32;
            unsigned af[4][4];
            unsigned bf[8][2];
#pragma unroll
            for (int i = 0; i < 4; ++i)
                ldsm4(af[i][0], af[i][1], af[i][2], af[i][3],
                      aBase + kOff + i * (16 * ROWB));
#pragma unroll
            for (int jp = 0; jp < 4; ++jp)
                ldsm4(bf[jp * 2][0], bf[jp * 2][1],
                      bf[jp * 2 + 1][0], bf[jp * 2 + 1][1],
                      bBase + kOff + jp * (16 * ROWB));
#pragma unroll
            for (int i = 0; i < 4; ++i)
#pragma unroll
                for (int j = 0; j < 8; ++j)
                    mma_f16(acc[i][j], af[i], bf[j][0], bf[j][1]);
        }
    }

    // Epilogue
    const float QS = 0.125f * 1.4426950408889634f;
#pragma unroll
    for (int i = 0; i < 4; ++i) {
        int m0 = bm + wm + i * 16 + lr;
#pragma unroll
        for (int j = 0; j < 8; ++j) {
            int n0 = bn + wn + j * 8 + lc * 2;
            float bia0 = bias[n0], bia1 = bias[n0 + 1];
            float v00 = acc[i][j].x + bia0;
            float v01 = acc[i][j].y + bia1;
            float v10 = acc[i][j].z + bia0;
            float v11 = acc[i][j].w + bia1;
            if (EPI == 1) {
                int b = m0 >> 11;
                int t = m0 & 2047;
                int h = n0 / 192;
                int rr = n0 - h * 192;
                int sel = rr >> 6;
                int d = rr & 63;
                if (sel == 0) {
                    __half* dst = g_q + (((size_t)(b * NH + h) * T_SEQ) + t) * HS + d;
                    *(__half2*)dst            = __floats2half2_rn(v00 * QS, v01 * QS);
                    *(__half2*)(dst + 8 * HS) = __floats2half2_rn(v10 * QS, v11 * QS);
                } else if (sel == 1) {
                    __half* dst = g_k + (((size_t)(b * NH + h) * T_SEQ) + t) * HS + d;
                    *(__half2*)dst            = __floats2half2_rn(v00, v01);
                    *(__half2*)(dst + 8 * HS) = __floats2half2_rn(v10, v11);
                } else {
                    __half* vb = g_v + ((size_t)(b * NH + h) * HS + d) * T_SEQ + t;
                    vb[0]         = __float2half_rn(v00);
                    vb[T_SEQ]     = __float2half_rn(v01);
                    vb[8]         = __float2half_rn(v10);
                    vb[T_SEQ + 8] = __float2half_rn(v11);
                }
            } else {
                float2 r0 = {v00, v01};
                float2 r1 = {v10, v11};
                *(float2*)(C + (size_t)m0 * N + n0) = r0;
                *(float2*)(C + (size_t)(m0 + 8) * N + n0) = r1;
            }
        }
    }
}

// ---------------------------------------------------------------------------
// Flash attention: 4 warps x 32 q-rows, fp16 mma, P in registers, MUFU exp2.
// K natural [c][d]; V^T [d][c]; both 64x64 halves, stride 144B, dbl-buffered.
// ---------------------------------------------------------------------------
#define KVB (64 * ROWB)
#define ATT_SMEM_BYTES (128 * ROWB + 4 * KVB)

__global__ __launch_bounds__(128, 2) void attn_f16_kernel()
{
    extern __shared__ char sma[];
    const unsigned qsA = (unsigned)__cvta_generic_to_shared(sma);
    const unsigned ksA = qsA + 128 * ROWB;
    const unsigned vsA = ksA + 2 * KVB;

    const int bh = blockIdx.y;
    const int qb = blockIdx.x;
    const __half* qp = g_q + ((size_t)bh * T_SEQ + (size_t)qb * 128) * HS;
    const __half* kp = g_k + (size_t)bh * T_SEQ * HS;
    const __half* vp = g_v + (size_t)bh * HS * T_SEQ;   // [d][t]

    const int tid  = threadIdx.x;
    const int lane = tid & 31;
    const int wid  = tid >> 5;           // 0..3
    const int lr   = lane >> 2;
    const int lc   = lane & 3;
    const int w32  = wid * 32;

    // LDSM lane maps
    const int rA = (lane & 7) + ((lane >> 3) & 1) * 8;
    const unsigned cA = ((lane >> 4) & 1) * 16;
    const int rB = (lane & 7) + ((lane >> 4) & 1) * 8;
    const unsigned cB = ((lane >> 3) & 1) * 16;

    const unsigned pQ = qsA + (w32 + rA) * ROWB + cA;
    const unsigned pK = ksA + rB * ROWB + cB;
    const unsigned pV = vsA + rB * ROWB + cB;

    auto issueKV = [&](int jc, int buf) {
        const __half* kj = kp + (size_t)jc * 64 * HS;
        const __half* vj = vp + (size_t)jc * 64;
#pragma unroll
        for (int it = 0; it < 4; ++it) {
            int u = tid + it * 128;       // 0..511
            int row = u >> 3;             // 0..63
            int ch  = u & 7;
            unsigned so = buf * KVB + row * ROWB + ch * 16;
            cp16(ksA + so, kj + (size_t)row * HS + ch * 8);
            cp16(vsA + so, vj + (size_t)row * T_SEQ + ch * 8);
        }
    };

    issueKV(0, 0);
    CP_COMMIT();

    // Stage Q (already fp16 + scaled): 128 rows x 64 halves
#pragma unroll
    for (int it = 0; it < 8; ++it) {
        int u = tid + it * 128;
        int row = u >> 3;
        int ch  = u & 7;
        *(uint4*)(sma + row * ROWB + ch * 16) =
            *(const uint4*)(qp + (size_t)row * HS + ch * 8);
    }
    __syncthreads();

    unsigned qf[4][2][4];                // [k16][m16 block]
#pragma unroll
    for (int kk = 0; kk < 4; ++kk)
#pragma unroll
        for (int im = 0; im < 2; ++im)
            ldsm4(qf[kk][im][0], qf[kk][im][1], qf[kk][im][2], qf[kk][im][3],
                  pQ + im * (16 * ROWB) + kk * 32);

    float4 o[2][8];
#pragma unroll
    for (int im = 0; im < 2; ++im)
#pragma unroll
        for (int j = 0; j < 8; ++j) o[im][j] = make_float4(0.f, 0.f, 0.f, 0.f);
    float mm[4] = {-1e30f, -1e30f, -1e30f, -1e30f};
    float ll[4] = {0.f, 0.f, 0.f, 0.f};

    for (int jc = 0; jc < T_SEQ / 64; ++jc) {
        const int cur = jc & 1;
        CP_WAIT0();
        __syncthreads();
        if (jc + 1 < T_SEQ / 64) { issueKV(jc + 1, cur ^ 1); CP_COMMIT(); }

        // S = Q K^T (warp 32x64)
        const unsigned pKc = pK + cur * KVB;
        float4 s[2][8];
#pragma unroll
        for (int im = 0; im < 2; ++im)
#pragma unroll
            for (int j = 0; j < 8; ++j) s[im][j] = make_float4(0.f, 0.f, 0.f, 0.f);
#pragma unroll
        for (int kk = 0; kk < 4; ++kk) {
            unsigned bf[8][2];
#pragma unroll
            for (int jp = 0; jp < 4; ++jp)
                ldsm4(bf[jp * 2][0], bf[jp * 2][1],
                      bf[jp * 2 + 1][0], bf[jp * 2 + 1][1],
                      pKc + kk * 32 + jp * (16 * ROWB));
#pragma unroll
            for (int im = 0; im < 2; ++im)
#pragma unroll
                for (int j = 0; j < 8; ++j)
                    mma_f16(s[im][j], qf[kk][im], bf[j][0], bf[j][1]);
        }

        // Online softmax (exp2 domain, MUFU), P stays in registers
#pragma unroll
        for (int im = 0; im < 2; ++im) {
            float mx0 = -1e30f, mx1 = -1e30f;
#pragma unroll
            for (int j = 0; j < 8; ++j) {
                mx0 = fmaxf(mx0, fmaxf(s[im][j].x, s[im][j].y));
                mx1 = fmaxf(mx1, fmaxf(s[im][j].z, s[im][j].w));
            }
            mx0 = fmaxf(mx0, __shfl_xor_sync(0xffffffffu, mx0, 1));
            mx0 = fmaxf(mx0, __shfl_xor_sync(0xffffffffu, mx0, 2));
            mx1 = fmaxf(mx1, __shfl_xor_sync(0xffffffffu, mx1, 1));
            mx1 = fmaxf(mx1, __shfl_xor_sync(0xffffffffu, mx1, 2));
            float mn0 = fmaxf(mm[im * 2], mx0);
            float mn1 = fmaxf(mm[im * 2 + 1], mx1);
            float a0 = ex2f(mm[im * 2] - mn0);
            float a1 = ex2f(mm[im * 2 + 1] - mn1);
            mm[im * 2] = mn0; mm[im * 2 + 1] = mn1;

            float s0 = 0.f, s1 = 0.f;
#pragma unroll
            for (int j = 0; j < 8; ++j) {
                float px = ex2f(s[im][j].x - mn0);
                float py = ex2f(s[im][j].y - mn0);
                float pz = ex2f(s[im][j].z - mn1);
                float pw = ex2f(s[im][j].w - mn1);
                s0 += px + py;
                s1 += pz + pw;
                s[im][j] = make_float4(px, py, pz, pw);
            }
            s0 += __shfl_xor_sync(0xffffffffu, s0, 1);
            s0 += __shfl_xor_sync(0xffffffffu, s0, 2);
            s1 += __shfl_xor_sync(0xffffffffu, s1, 1);
            s1 += __shfl_xor_sync(0xffffffffu, s1, 2);
            ll[im * 2]     = ll[im * 2] * a0 + s0;
            ll[im * 2 + 1] = ll[im * 2 + 1] * a1 + s1;
#pragma unroll
            for (int j = 0; j < 8; ++j) {
                o[im][j].x *= a0; o[im][j].y *= a0;
                o[im][j].z *= a1; o[im][j].w *= a1;
            }
        }

        // O += P V : A frags packed directly from exp'd S fragments
        const unsigned pVc = pV + cur * KVB;
#pragma unroll
        for (int kk = 0; kk < 4; ++kk) {
            unsigned bf[8][2];
#pragma unroll
            for (int jp = 0; jp < 4; ++jp)
                ldsm4(bf[jp * 2][0], bf[jp * 2][1],
                      bf[jp * 2 + 1][0], bf[jp * 2 + 1][1],
                      pVc + kk * 32 + jp * (16 * ROWB));
#pragma unroll
            for (int im = 0; im < 2; ++im) {
                unsigned a_[4];
                a_[0] = h2u(__floats2half2_rn(s[im][2 * kk].x,     s[im][2 * kk].y));
                a_[1] = h2u(__floats2half2_rn(s[im][2 * kk].z,     s[im][2 * kk].w));
                a_[2] = h2u(__floats2half2_rn(s[im][2 * kk + 1].x, s[im][2 * kk + 1].y));
                a_[3] = h2u(__floats2half2_rn(s[im][2 * kk + 1].z, s[im][2 * kk + 1].w));
#pragma unroll
                for (int j = 0; j < 8; ++j)
                    mma_f16(o[im][j], a_, bf[j][0], bf[j][1]);
            }
        }
    }

    // Epilogue: normalize, emit fp16 into g_attv
    const int b = bh >> 4;
    const int h = bh & 15;
#pragma unroll
    for (int im = 0; im < 2; ++im) {
        float inv0 = 1.0f / ll[im * 2];
        float inv1 = 1.0f / ll[im * 2 + 1];
        const int t0 = qb * 128 + w32 + im * 16 + lr;
#pragma unroll
        for (int j = 0; j < 8; ++j) {
            int col = h * 64 + j * 8 + lc * 2;
            *(__half2*)(g_attv + (size_t)(b * T_SEQ + t0) * CDIM + col) =
                __floats2half2_rn(o[im][j].x * inv0, o[im][j].y * inv0);
            *(__half2*)(g_attv + (size_t)(b * T_SEQ + t0 + 8) * CDIM + col) =
                __floats2half2_rn(o[im][j].z * inv1, o[im][j].w * inv1);
        }
    }
}

// ---------------------------------------------------------------------------
extern "C" void kernel_launch(void* const* d_in, const int* in_sizes, int n_in,
                              void* d_out, int out_size)
{
    const float* x    = (const float*)d_in[0];
    const float* Wqkv = (const float*)d_in[1];
    const float* bqkv = (const float*)d_in[2];
    const float* Wout = (const float*)d_in[3];
    const float* bout = (const float*)d_in[4];
    float* out = (float*)d_out;

    cudaFuncSetAttribute(gemm_f16<1>, cudaFuncAttributeMaxDynamicSharedMemorySize, GEMM_SMEM_BYTES);
    cudaFuncSetAttribute(gemm_f16<2>, cudaFuncAttributeMaxDynamicSharedMemorySize, GEMM_SMEM_BYTES);
    cudaFuncSetAttribute(attn_f16_kernel, cudaFuncAttributeMaxDynamicSharedMemorySize, ATT_SMEM_BYTES);

    __half* d_xa;  cudaGetSymbolAddress((void**)&d_xa, g_xa);
    __half* d_wq;  cudaGetSymbolAddress((void**)&d_wq, g_wqkv);
    __half* d_wo;  cudaGetSymbolAddress((void**)&d_wo, g_wout);

    // Pre-convert operands to fp16 (RN)
    cvt_f16_kernel<<<592, 256>>>((const float4*)x,    (uint4*)d_xa, MROWS * CDIM / 8);
    cvt_f16_kernel<<<592, 256>>>((const float4*)Wqkv, (uint4*)d_wq, 3 * CDIM * CDIM / 8);
    cvt_f16_kernel<<<592, 256>>>((const float4*)Wout, (uint4*)d_wo, CDIM * CDIM / 8);

    // QKV projection: M=8192, N=3072, K=1024 -> q/k natural, v transposed
    gemm_f16<1><<<dim3(3072 / 128, MROWS / 128), 128, GEMM_SMEM_BYTES>>>(
        bqkv, nullptr, 3 * CDIM);

    // Attention
    attn_f16_kernel<<<dim3(T_SEQ / 128, BATCH * NH), 128, ATT_SMEM_BYTES>>>();

    // Output projection: M=8192, N=1024, K=1024
    gemm_f16<2><<<dim3(CDIM / 128, MROWS / 128), 128, GEMM_SMEM_BYTES>>>(
        bout, out, CDIM);
}